// round 15
// baseline (speedup 1.0000x reference)
#include <cuda_runtime.h>
#include <cuda_fp16.h>
#include <cstdint>
#include <cstddef>

// ---------------- problem constants ----------------
#define TOKENS 8192
#define KDIM   4096
#define ODIM   4096

#define BM 128
#define BN 128
#define BK 64
#define KT (KDIM / BK)      // 64 k-iterations
#define STAGES 3
#define NTHREADS 256        // 8 warps in 2x4, warp tile 64x32

#define A_STAGE_BYTES (BM * BK * 2)
#define B_STAGE_BYTES (BN * BK * 2)
#define STAGE_BYTES   (A_STAGE_BYTES + B_STAGE_BYTES)   // 32768
#define SMEM_TOTAL    (STAGES * STAGE_BYTES)            // 98304 -> 2 CTAs/SM

// ---------------- scratch (no runtime allocation allowed) ----------------
__device__ __half g_xh[(size_t)TOKENS * KDIM];   // 64 MB
__device__ __half g_wq[(size_t)ODIM * KDIM];     // 32 MB

// ---------------- helpers ----------------
__device__ __forceinline__ uint32_t smem_to_u32(const void* p) {
    uint32_t a;
    asm("{ .reg .u64 t; cvta.to.shared.u64 t, %1; cvt.u32.u64 %0, t; }" : "=r"(a) : "l"(p));
    return a;
}
__device__ __forceinline__ uint32_t sw128(uint32_t off) {
    return off ^ ((off >> 3) & 0x70);
}
__device__ __forceinline__ void cp_async16(uint32_t dst, const void* src) {
    asm volatile("cp.async.cg.shared.global [%0], [%1], 16;" :: "r"(dst), "l"(src));
}
__device__ __forceinline__ void cp_commit() {
    asm volatile("cp.async.commit_group;" ::: "memory");
}
template <int N>
__device__ __forceinline__ void cp_wait() {
    asm volatile("cp.async.wait_group %0;" :: "n"(N) : "memory");
}
__device__ __forceinline__ void ldsm4(uint32_t* r, uint32_t addr) {
    asm volatile("ldmatrix.sync.aligned.m8n8.x4.shared.b16 {%0,%1,%2,%3}, [%4];"
                 : "=r"(r[0]), "=r"(r[1]), "=r"(r[2]), "=r"(r[3]) : "r"(addr));
}
__device__ __forceinline__ void mma16816(float* c, const uint32_t* a,
                                         uint32_t b0, uint32_t b1) {
    asm volatile(
        "mma.sync.aligned.m16n8k16.row.col.f32.f16.f16.f32 "
        "{%0,%1,%2,%3}, {%4,%5,%6,%7}, {%8,%9}, {%0,%1,%2,%3};"
        : "+f"(c[0]), "+f"(c[1]), "+f"(c[2]), "+f"(c[3])
        : "r"(a[0]), "r"(a[1]), "r"(a[2]), "r"(a[3]), "r"(b0), "r"(b1));
}

// ---------------- fused prep kernel ----------------
// Quantizer: levels {±(L+S), ±(L−S)}, thresholds {−L, 0, L}
// => q = sgn(w) * (L + (|w| > L ? S : -S)).   (ILP = 2 float4 per thread)
#define W_N4   (ODIM * KDIM / 4)
#define X_N4   (TOKENS * KDIM / 4)
#define WBLKS  ((W_N4 / 2 + 255) / 256)
#define XBLKS  ((X_N4 / 2 + 255) / 256)

__global__ void prep_kernel(const float* __restrict__ w,
                            const float* __restrict__ x,
                            const float* __restrict__ basis) {
    int b = blockIdx.x;
    if (b < WBLKS) {
        float b0 = fabsf(basis[0]), b1 = fabsf(basis[1]);
        float L = fmaxf(b0, b1), S = fminf(b0, b1);
        int i0 = (b * blockDim.x + threadIdx.x) * 2;
#pragma unroll
        for (int u = 0; u < 2; u++) {
            int i = i0 + u;
            if (i >= W_N4) return;
            float4 v = reinterpret_cast<const float4*>(w)[i];
            float m0 = L + ((fabsf(v.x) > L) ? S : -S);
            float m1 = L + ((fabsf(v.y) > L) ? S : -S);
            float m2 = L + ((fabsf(v.z) > L) ? S : -S);
            float m3 = L + ((fabsf(v.w) > L) ? S : -S);
            __half2 p0 = __floats2half2_rn(copysignf(m0, v.x), copysignf(m1, v.y));
            __half2 p1 = __floats2half2_rn(copysignf(m2, v.z), copysignf(m3, v.w));
            uint2 o;
            o.x = *reinterpret_cast<uint32_t*>(&p0);
            o.y = *reinterpret_cast<uint32_t*>(&p1);
            reinterpret_cast<uint2*>(g_wq)[i] = o;
        }
    } else {
        int i0 = ((b - WBLKS) * blockDim.x + threadIdx.x) * 2;
#pragma unroll
        for (int u = 0; u < 2; u++) {
            int i = i0 + u;
            if (i >= X_N4) return;
            float4 v = reinterpret_cast<const float4*>(x)[i];
            __half2 a = __floats2half2_rn(v.x, v.y);
            __half2 c = __floats2half2_rn(v.z, v.w);
            uint2 o;
            o.x = *reinterpret_cast<uint32_t*>(&a);
            o.y = *reinterpret_cast<uint32_t*>(&c);
            reinterpret_cast<uint2*>(g_xh)[i] = o;
        }
    }
}

// ---------------- GEMM ----------------
struct Ctx {
    uint32_t sb;
    uint32_t a_base0, b_base0;
    const __half* gA;
    const __half* gB;
    int tid;
};

template <int S>
__device__ __forceinline__ void load_A(const Ctx& c, int kt) {
    uint32_t a_off = c.sb + S * STAGE_BYTES;
#pragma unroll
    for (int p = 0; p < 4; p++) {
        int id = c.tid + p * NTHREADS;
        int row = id >> 3, ch = id & 7;
        uint32_t off = (uint32_t)row * 128 + (uint32_t)ch * 16;
        cp_async16(a_off + sw128(off),
                   c.gA + (size_t)row * KDIM + kt * BK + ch * 8);
    }
}
template <int S>
__device__ __forceinline__ void load_B(const Ctx& c, int kt) {
    uint32_t b_off = c.sb + S * STAGE_BYTES + A_STAGE_BYTES;
#pragma unroll
    for (int p = 0; p < 4; p++) {
        int id = c.tid + p * NTHREADS;
        int row = id >> 3, ch = id & 7;
        uint32_t off = (uint32_t)row * 128 + (uint32_t)ch * 16;
        cp_async16(b_off + sw128(off),
                   c.gB + (size_t)row * KDIM + kt * BK + ch * 8);
    }
}

// One kt-iteration on stage CUR (compile-time stage indices).
// Entry contract: stage CUR is complete AND visible to all threads (the
// previous iteration ended with cp_wait<1> + __syncthreads), and CUR's kk0
// fragments are already in af[0]/bf[0].
// Exit: performed cp_wait<1>+__syncthreads (unless last iter) and loaded
// stage NXT's kk0 fragments — race-free by the wait-then-barrier pattern.
template <int CUR>
__device__ __forceinline__ void iter(const Ctx& c, int kt,
                                     float acc[4][4][4],
                                     uint32_t af[2][4][4],
                                     uint32_t bf[2][2][4]) {
    constexpr int NXT = (CUR + 1) % STAGES;      // stage of kt+1
    constexpr int LDS = (CUR + 2) % STAGES;      // stage to fill (kt+2)

    uint32_t a_base = c.sb + CUR * STAGE_BYTES + c.a_base0;
    uint32_t b_base = c.sb + CUR * STAGE_BYTES + A_STAGE_BYTES + c.b_base0;
    bool have_next = (kt + STAGES - 1) < KT;

    // prefetch kk1 fragments (latency hidden under kk0's MMA burst)
    {
        uint32_t ax = a_base ^ 32u, bx = b_base ^ 32u;
#pragma unroll
        for (int i = 0; i < 4; i++) ldsm4(af[1][i], ax + i * 2048);
#pragma unroll
        for (int g = 0; g < 2; g++) ldsm4(bf[1][g], bx + g * 2048);
    }
    // kk0 MMA burst
#pragma unroll
    for (int i = 0; i < 4; i++)
#pragma unroll
        for (int j = 0; j < 4; j++)
            mma16816(acc[i][j], af[0][i],
                     bf[0][j >> 1][j & 1], bf[0][j >> 1][(j & 1) + 2]);

    // A-half of next-stage loads under kk0 drain (stage LDS: its last
    // readers finished before the barrier at the end of iter(kt-1))
    if (have_next) load_A<LDS>(c, kt + STAGES - 1);

    // prefetch kk2
    {
        uint32_t ax = a_base ^ 64u, bx = b_base ^ 64u;
#pragma unroll
        for (int i = 0; i < 4; i++) ldsm4(af[0][i], ax + i * 2048);
#pragma unroll
        for (int g = 0; g < 2; g++) ldsm4(bf[0][g], bx + g * 2048);
    }
    // kk1 MMA burst
#pragma unroll
    for (int i = 0; i < 4; i++)
#pragma unroll
        for (int j = 0; j < 4; j++)
            mma16816(acc[i][j], af[1][i],
                     bf[1][j >> 1][j & 1], bf[1][j >> 1][(j & 1) + 2]);

    // B-half of next-stage loads + commit (exactly one group per iter)
    if (have_next) load_B<LDS>(c, kt + STAGES - 1);
    cp_commit();

    // prefetch kk3 (last read of stage CUR)
    {
        uint32_t ax = a_base ^ 96u, bx = b_base ^ 96u;
#pragma unroll
        for (int i = 0; i < 4; i++) ldsm4(af[1][i], ax + i * 2048);
#pragma unroll
        for (int g = 0; g < 2; g++) ldsm4(bf[1][g], bx + g * 2048);
    }
    // kk2 MMA burst
#pragma unroll
    for (int i = 0; i < 4; i++)
#pragma unroll
        for (int j = 0; j < 4; j++)
            mma16816(acc[i][j], af[0][i],
                     bf[0][j >> 1][j & 1], bf[0][j >> 1][(j & 1) + 2]);

    if (kt + 1 < KT) {
        // SAFE handoff: every thread waits for its own cp.asyncs of stage
        // NXT (wait<1>: outstanding = {G(kt+1), G(kt+2)} -> G(kt+1) done),
        // THEN barrier => collectively stage NXT complete & visible.
        cp_wait<1>();
        __syncthreads();
    }

    // kk3 MMA burst — operands in registers, issues immediately post-barrier
#pragma unroll
    for (int i = 0; i < 4; i++)
#pragma unroll
        for (int j = 0; j < 4; j++)
            mma16816(acc[i][j], af[1][i],
                     bf[1][j >> 1][j & 1], bf[1][j >> 1][(j & 1) + 2]);

    if (kt + 1 < KT) {
        // next stage's kk0 fragments (race-free after the barrier above);
        // LDS latency hidden under the kk3 burst drain.
        uint32_t an = c.sb + NXT * STAGE_BYTES + c.a_base0;
        uint32_t bn = c.sb + NXT * STAGE_BYTES + A_STAGE_BYTES + c.b_base0;
#pragma unroll
        for (int i = 0; i < 4; i++) ldsm4(af[0][i], an + i * 2048);
#pragma unroll
        for (int g = 0; g < 2; g++) ldsm4(bf[0][g], bn + g * 2048);
    }
}

__global__ void __launch_bounds__(NTHREADS, 2)
gemm_kernel(const float* __restrict__ bias, float* __restrict__ out) {
    extern __shared__ char smem[];
    Ctx c;
    c.sb = smem_to_u32(smem);
    c.tid = threadIdx.x;
    int wid = c.tid >> 5, lane = c.tid & 31;
    int warp_m = wid >> 2;            // 0..1  (64 rows each)
    int warp_n = wid & 3;             // 0..3  (32 cols each)
    int nbase = blockIdx.x * BN;
    int mbase = blockIdx.y * BM;

    c.gA = g_xh + (size_t)mbase * KDIM;
    c.gB = g_wq + (size_t)nbase * KDIM;

    float acc[4][4][4];
#pragma unroll
    for (int i = 0; i < 4; i++)
#pragma unroll
        for (int j = 0; j < 4; j++)
#pragma unroll
            for (int r = 0; r < 4; r++) acc[i][j][r] = 0.f;

    // XOR swizzle iterator: address for chunk (ch0 + 2*kk) of a row is
    //   lane_base(row) ^ (kk << 5)     [bits disjoint, no carries]
    int a_row = warp_m * 64 + ((lane >> 3) & 1) * 8 + (lane & 7);
    int b_row = warp_n * 32 + ((lane >> 3) & 1) * 8 + (lane & 7);
    int ch0 = lane >> 4;              // 0..1
    c.a_base0 = (uint32_t)a_row * 128 + 16u * (uint32_t)(ch0 ^ (a_row & 7));
    c.b_base0 = (uint32_t)b_row * 128 + 16u * (uint32_t)(ch0 ^ (b_row & 7));

    // prologue: fill stages 0,1
    load_A<0>(c, 0); load_B<0>(c, 0); cp_commit();
    load_A<1>(c, 1); load_B<1>(c, 1); cp_commit();

    uint32_t af[2][4][4], bf[2][2][4];

    // safe entry: all threads wait for stage 0, barrier, then read kk0 frags
    cp_wait<1>();
    __syncthreads();
    {
        uint32_t a0 = c.sb + c.a_base0;
        uint32_t b0 = c.sb + A_STAGE_BYTES + c.b_base0;
#pragma unroll
        for (int i = 0; i < 4; i++) ldsm4(af[0][i], a0 + i * 2048);
#pragma unroll
        for (int g = 0; g < 2; g++) ldsm4(bf[0][g], b0 + g * 2048);
    }

    // KT = 64 = 3*21 + 1: stage-constant triples + one tail iteration
#pragma unroll 1
    for (int ktb = 0; ktb < 63; ktb += 3) {
        iter<0>(c, ktb + 0, acc, af, bf);
        iter<1>(c, ktb + 1, acc, af, bf);
        iter<2>(c, ktb + 2, acc, af, bf);
    }
    iter<0>(c, 63, acc, af, bf);

    // epilogue: direct to gmem with bias
    int m0 = mbase + warp_m * 64 + (lane >> 2);
    int n0 = nbase + warp_n * 32 + (lane & 3) * 2;
    float2 bj[4];
#pragma unroll
    for (int j = 0; j < 4; j++)
        bj[j] = *reinterpret_cast<const float2*>(bias + n0 + j * 8);
#pragma unroll
    for (int i = 0; i < 4; i++) {
        float* row_lo = out + (size_t)(m0 + i * 16) * ODIM;
        float* row_hi = out + (size_t)(m0 + i * 16 + 8) * ODIM;
#pragma unroll
        for (int j = 0; j < 4; j++) {
            float2 lo = { acc[i][j][0] + bj[j].x, acc[i][j][1] + bj[j].y };
            float2 hi = { acc[i][j][2] + bj[j].x, acc[i][j][3] + bj[j].y };
            *reinterpret_cast<float2*>(row_lo + n0 + j * 8) = lo;
            *reinterpret_cast<float2*>(row_hi + n0 + j * 8) = hi;
        }
    }
}

// ---------------- launch ----------------
extern "C" void kernel_launch(void* const* d_in, const int* in_sizes, int n_in,
                              void* d_out, int out_size) {
    const float* x     = (const float*)d_in[0];
    const float* w     = (const float*)d_in[1];
    const float* bias  = (const float*)d_in[2];
    const float* basis = (const float*)d_in[3];
    float* out = (float*)d_out;

    cudaFuncSetAttribute(gemm_kernel, cudaFuncAttributeMaxDynamicSharedMemorySize,
                         SMEM_TOTAL);

    prep_kernel<<<WBLKS + XBLKS, 256>>>(w, x, basis);
    gemm_kernel<<<dim3(ODIM / BN, TOKENS / BM), NTHREADS, SMEM_TOTAL>>>(bias, out);
}

// round 16
// speedup vs baseline: 1.1171x; 1.1171x over previous
#include <cuda_runtime.h>
#include <cuda_fp16.h>
#include <cstdint>
#include <cstddef>

// ---------------- problem constants ----------------
#define TOKENS 8192
#define KDIM   4096
#define ODIM   4096

#define BM 128
#define BN 128
#define BK 64
#define KT (KDIM / BK)      // 64 k-iterations
#define STAGES 3
#define NTHREADS 256        // 8 warps in 2x4, warp tile 64x32

#define A_STAGE_BYTES (BM * BK * 2)
#define B_STAGE_BYTES (BN * BK * 2)
#define STAGE_BYTES   (A_STAGE_BYTES + B_STAGE_BYTES)   // 32768
#define SMEM_TOTAL    (STAGES * STAGE_BYTES)            // 98304 -> 2 CTAs/SM

// ---------------- scratch (no runtime allocation allowed) ----------------
__device__ __half g_xh[(size_t)TOKENS * KDIM];   // 64 MB
__device__ __half g_wq[(size_t)ODIM * KDIM];     // 32 MB

// ---------------- helpers ----------------
__device__ __forceinline__ uint32_t smem_to_u32(const void* p) {
    uint32_t a;
    asm("{ .reg .u64 t; cvta.to.shared.u64 t, %1; cvt.u32.u64 %0, t; }" : "=r"(a) : "l"(p));
    return a;
}
__device__ __forceinline__ uint32_t sw128(uint32_t off) {
    return off ^ ((off >> 3) & 0x70);
}
__device__ __forceinline__ void cp_async16(uint32_t dst, const void* src) {
    asm volatile("cp.async.cg.shared.global [%0], [%1], 16;" :: "r"(dst), "l"(src));
}
__device__ __forceinline__ void cp_commit() {
    asm volatile("cp.async.commit_group;" ::: "memory");
}
template <int N>
__device__ __forceinline__ void cp_wait() {
    asm volatile("cp.async.wait_group %0;" :: "n"(N) : "memory");
}
__device__ __forceinline__ void ldsm4(uint32_t* r, uint32_t addr) {
    asm volatile("ldmatrix.sync.aligned.m8n8.x4.shared.b16 {%0,%1,%2,%3}, [%4];"
                 : "=r"(r[0]), "=r"(r[1]), "=r"(r[2]), "=r"(r[3]) : "r"(addr));
}
__device__ __forceinline__ void mma16816(float* c, const uint32_t* a,
                                         uint32_t b0, uint32_t b1) {
    asm volatile(
        "mma.sync.aligned.m16n8k16.row.col.f32.f16.f16.f32 "
        "{%0,%1,%2,%3}, {%4,%5,%6,%7}, {%8,%9}, {%0,%1,%2,%3};"
        : "+f"(c[0]), "+f"(c[1]), "+f"(c[2]), "+f"(c[3])
        : "r"(a[0]), "r"(a[1]), "r"(a[2]), "r"(a[3]), "r"(b0), "r"(b1));
}

// ---------------- fused prep kernel ----------------
// Quantizer: levels {±(L+S), ±(L−S)}, thresholds {−L, 0, L}
// => q = sgn(w) * (L + (|w| > L ? S : -S)).   (ILP = 2 float4 per thread)
#define W_N4   (ODIM * KDIM / 4)
#define X_N4   (TOKENS * KDIM / 4)
#define WBLKS  ((W_N4 / 2 + 255) / 256)
#define XBLKS  ((X_N4 / 2 + 255) / 256)

__global__ void prep_kernel(const float* __restrict__ w,
                            const float* __restrict__ x,
                            const float* __restrict__ basis) {
    int b = blockIdx.x;
    if (b < WBLKS) {
        float b0 = fabsf(basis[0]), b1 = fabsf(basis[1]);
        float L = fmaxf(b0, b1), S = fminf(b0, b1);
        int i0 = (b * blockDim.x + threadIdx.x) * 2;
#pragma unroll
        for (int u = 0; u < 2; u++) {
            int i = i0 + u;
            if (i >= W_N4) return;
            float4 v = reinterpret_cast<const float4*>(w)[i];
            float m0 = L + ((fabsf(v.x) > L) ? S : -S);
            float m1 = L + ((fabsf(v.y) > L) ? S : -S);
            float m2 = L + ((fabsf(v.z) > L) ? S : -S);
            float m3 = L + ((fabsf(v.w) > L) ? S : -S);
            __half2 p0 = __floats2half2_rn(copysignf(m0, v.x), copysignf(m1, v.y));
            __half2 p1 = __floats2half2_rn(copysignf(m2, v.z), copysignf(m3, v.w));
            uint2 o;
            o.x = *reinterpret_cast<uint32_t*>(&p0);
            o.y = *reinterpret_cast<uint32_t*>(&p1);
            reinterpret_cast<uint2*>(g_wq)[i] = o;
        }
    } else {
        int i0 = ((b - WBLKS) * blockDim.x + threadIdx.x) * 2;
#pragma unroll
        for (int u = 0; u < 2; u++) {
            int i = i0 + u;
            if (i >= X_N4) return;
            float4 v = reinterpret_cast<const float4*>(x)[i];
            __half2 a = __floats2half2_rn(v.x, v.y);
            __half2 c = __floats2half2_rn(v.z, v.w);
            uint2 o;
            o.x = *reinterpret_cast<uint32_t*>(&a);
            o.y = *reinterpret_cast<uint32_t*>(&c);
            reinterpret_cast<uint2*>(g_xh)[i] = o;
        }
    }
}

// ---------------- GEMM ----------------
struct Ctx {
    uint32_t sb;
    uint32_t a_base0, b_base0;
    const __half* gA;
    const __half* gB;
    int tid;
};

template <int S>
__device__ __forceinline__ void load_A(const Ctx& c, int kt) {
    uint32_t a_off = c.sb + S * STAGE_BYTES;
#pragma unroll
    for (int p = 0; p < 4; p++) {
        int id = c.tid + p * NTHREADS;
        int row = id >> 3, ch = id & 7;
        uint32_t off = (uint32_t)row * 128 + (uint32_t)ch * 16;
        cp_async16(a_off + sw128(off),
                   c.gA + (size_t)row * KDIM + kt * BK + ch * 8);
    }
}
template <int S>
__device__ __forceinline__ void load_B(const Ctx& c, int kt) {
    uint32_t b_off = c.sb + S * STAGE_BYTES + A_STAGE_BYTES;
#pragma unroll
    for (int p = 0; p < 4; p++) {
        int id = c.tid + p * NTHREADS;
        int row = id >> 3, ch = id & 7;
        uint32_t off = (uint32_t)row * 128 + (uint32_t)ch * 16;
        cp_async16(b_off + sw128(off),
                   c.gB + (size_t)row * KDIM + kt * BK + ch * 8);
    }
}

#define MMA_BURST(buf)                                                  \
    _Pragma("unroll")                                                   \
    for (int i = 0; i < 4; i++)                                         \
        _Pragma("unroll")                                               \
        for (int j = 0; j < 4; j++)                                     \
            mma16816(acc[i][j], af[buf][i],                             \
                     bf[buf][j >> 1][j & 1], bf[buf][j >> 1][(j & 1) + 2]);

#define LDSM_GROUP(buf, base_a, base_b, x)  do {                        \
    uint32_t _ax = (base_a) ^ (uint32_t)(x);                            \
    uint32_t _bx = (base_b) ^ (uint32_t)(x);                            \
    _Pragma("unroll")                                                   \
    for (int i = 0; i < 4; i++) ldsm4(af[buf][i], _ax + i * 2048);      \
    _Pragma("unroll")                                                   \
    for (int g = 0; g < 2; g++) ldsm4(bf[buf][g], _bx + g * 2048);      \
} while (0)

// Rotated iteration for stage CUR = kt % 3 (compile-time).
// Entry: buffer1 holds kk3 fragments of stage kt-1; all threads have done
//        cp_wait<1> for stage kt (in the previous iteration).
// Order: barrier -> ldsm kk0(cur) -> MMA kk3(prev)(armed) -> ... -> ldsm
//        kk3(cur) at the end. Every ldsm reading stage kt sits AFTER the
//        barrier => race-free; first post-barrier tensor work is armed.
template <int CUR>
__device__ __forceinline__ void iter(const Ctx& c, int kt,
                                     float acc[4][4][4],
                                     uint32_t af[2][4][4],
                                     uint32_t bf[2][2][4]) {
    constexpr int LDS = (CUR + 2) % STAGES;      // stage slot for kt+2

    // All threads completed cp_wait<1> for stage kt before this barrier:
    // post-barrier, stage kt is complete & visible. Also closes the WAR
    // window for refilling slot LDS (its last reader was iter kt-1).
    __syncthreads();

    uint32_t a_base = c.sb + CUR * STAGE_BYTES + c.a_base0;
    uint32_t b_base = c.sb + CUR * STAGE_BYTES + A_STAGE_BYTES + c.b_base0;
    bool have_next = (kt + 2) < KT;

    LDSM_GROUP(0, a_base, b_base, 0);    // kk0 frags (post-barrier, safe)
    MMA_BURST(1);                        // kk3 of PREVIOUS stage (armed)
    LDSM_GROUP(1, a_base, b_base, 32);   // kk1 frags
    MMA_BURST(0);                        // kk0
    if (have_next) load_A<LDS>(c, kt + 2);
    LDSM_GROUP(0, a_base, b_base, 64);   // kk2 frags
    MMA_BURST(1);                        // kk1
    if (have_next) load_B<LDS>(c, kt + 2);
    cp_commit();
    cp_wait<1>();                        // group(kt+1) done (this thread);
                                         // skew absorbed before next barrier
    MMA_BURST(0);                        // kk2
    LDSM_GROUP(1, a_base, b_base, 96);   // kk3 frags (stage kt, still safe)
}

__global__ void __launch_bounds__(NTHREADS, 2)
gemm_kernel(const float* __restrict__ bias, float* __restrict__ out) {
    extern __shared__ char smem[];
    Ctx c;
    c.sb = smem_to_u32(smem);
    c.tid = threadIdx.x;
    int wid = c.tid >> 5, lane = c.tid & 31;
    int warp_m = wid >> 2;            // 0..1  (64 rows each)
    int warp_n = wid & 3;             // 0..3  (32 cols each)
    int nbase = blockIdx.x * BN;
    int mbase = blockIdx.y * BM;

    c.gA = g_xh + (size_t)mbase * KDIM;
    c.gB = g_wq + (size_t)nbase * KDIM;

    float acc[4][4][4];
#pragma unroll
    for (int i = 0; i < 4; i++)
#pragma unroll
        for (int j = 0; j < 4; j++)
#pragma unroll
            for (int r = 0; r < 4; r++) acc[i][j][r] = 0.f;

    // XOR swizzle iterator: address for chunk (ch0 + 2*kk) of a row is
    //   lane_base(row) ^ (kk << 5)     [bits disjoint, no carries]
    int a_row = warp_m * 64 + ((lane >> 3) & 1) * 8 + (lane & 7);
    int b_row = warp_n * 32 + ((lane >> 3) & 1) * 8 + (lane & 7);
    int ch0 = lane >> 4;              // 0..1
    c.a_base0 = (uint32_t)a_row * 128 + 16u * (uint32_t)(ch0 ^ (a_row & 7));
    c.b_base0 = (uint32_t)b_row * 128 + 16u * (uint32_t)(ch0 ^ (b_row & 7));

    // prologue: fill stages 0,1
    load_A<0>(c, 0); load_B<0>(c, 0); cp_commit();
    load_A<1>(c, 1); load_B<1>(c, 1); cp_commit();

    uint32_t af[2][4][4], bf[2][2][4];

    // peeled iteration kt=0 (no previous kk3 burst)
    cp_wait<1>();                        // stage 0 done (this thread)
    __syncthreads();                     // stage 0 visible to all
    {
        uint32_t a_base = c.sb + c.a_base0;
        uint32_t b_base = c.sb + A_STAGE_BYTES + c.b_base0;
        LDSM_GROUP(0, a_base, b_base, 0);     // kk0
        LDSM_GROUP(1, a_base, b_base, 32);    // kk1
        MMA_BURST(0);                         // kk0
        load_A<2>(c, 2);
        LDSM_GROUP(0, a_base, b_base, 64);    // kk2
        MMA_BURST(1);                         // kk1
        load_B<2>(c, 2);
        cp_commit();
        cp_wait<1>();                         // group(1) done
        MMA_BURST(0);                         // kk2
        LDSM_GROUP(1, a_base, b_base, 96);    // kk3 frags of stage 0
    }

    // kt = 1..63 : 63 iterations = 21 stage-constant triples <1>,<2>,<0>
#pragma unroll 1
    for (int ktb = 1; ktb < 64; ktb += 3) {
        iter<1>(c, ktb + 0, acc, af, bf);
        iter<2>(c, ktb + 1, acc, af, bf);
        iter<0>(c, ktb + 2, acc, af, bf);
    }
    // final kk3 burst of stage 63 (frags loaded at end of iter kt=63)
    MMA_BURST(1);

    // epilogue: direct to gmem with bias
    int m0 = mbase + warp_m * 64 + (lane >> 2);
    int n0 = nbase + warp_n * 32 + (lane & 3) * 2;
    float2 bj[4];
#pragma unroll
    for (int j = 0; j < 4; j++)
        bj[j] = *reinterpret_cast<const float2*>(bias + n0 + j * 8);
#pragma unroll
    for (int i = 0; i < 4; i++) {
        float* row_lo = out + (size_t)(m0 + i * 16) * ODIM;
        float* row_hi = out + (size_t)(m0 + i * 16 + 8) * ODIM;
#pragma unroll
        for (int j = 0; j < 4; j++) {
            float2 lo = { acc[i][j][0] + bj[j].x, acc[i][j][1] + bj[j].y };
            float2 hi = { acc[i][j][2] + bj[j].x, acc[i][j][3] + bj[j].y };
            *reinterpret_cast<float2*>(row_lo + n0 + j * 8) = lo;
            *reinterpret_cast<float2*>(row_hi + n0 + j * 8) = hi;
        }
    }
}

// ---------------- launch ----------------
extern "C" void kernel_launch(void* const* d_in, const int* in_sizes, int n_in,
                              void* d_out, int out_size) {
    const float* x     = (const float*)d_in[0];
    const float* w     = (const float*)d_in[1];
    const float* bias  = (const float*)d_in[2];
    const float* basis = (const float*)d_in[3];
    float* out = (float*)d_out;

    cudaFuncSetAttribute(gemm_kernel, cudaFuncAttributeMaxDynamicSharedMemorySize,
                         SMEM_TOTAL);

    prep_kernel<<<WBLKS + XBLKS, 256>>>(w, x, basis);
    gemm_kernel<<<dim3(ODIM / BN, TOKENS / BM), NTHREADS, SMEM_TOTAL>>>(bias, out);
}

// round 17
// speedup vs baseline: 1.1246x; 1.0067x over previous
#include <cuda_runtime.h>
#include <cuda_fp16.h>
#include <cstdint>
#include <cstddef>

// ---------------- problem constants ----------------
#define TOKENS 8192
#define KDIM   4096
#define ODIM   4096

#define BM 128
#define BN 128
#define BK 64
#define KT (KDIM / BK)      // 64 k-iterations
#define STAGES 3
#define NTHREADS 256        // 8 warps in 2x4, warp tile 64x32

#define A_STAGE_BYTES (BM * BK * 2)
#define B_STAGE_BYTES (BN * BK * 2)
#define STAGE_BYTES   (A_STAGE_BYTES + B_STAGE_BYTES)   // 32768
#define SMEM_TOTAL    (STAGES * STAGE_BYTES)            // 98304 -> 2 CTAs/SM

// ---------------- scratch (no runtime allocation allowed) ----------------
__device__ __half g_xh[(size_t)TOKENS * KDIM];   // 64 MB
__device__ __half g_wq[(size_t)ODIM * KDIM];     // 32 MB

// ---------------- helpers ----------------
__device__ __forceinline__ uint32_t smem_to_u32(const void* p) {
    uint32_t a;
    asm("{ .reg .u64 t; cvta.to.shared.u64 t, %1; cvt.u32.u64 %0, t; }" : "=r"(a) : "l"(p));
    return a;
}
__device__ __forceinline__ uint32_t sw128(uint32_t off) {
    return off ^ ((off >> 3) & 0x70);
}
__device__ __forceinline__ void cp_async16(uint32_t dst, const void* src) {
    asm volatile("cp.async.cg.shared.global [%0], [%1], 16;" :: "r"(dst), "l"(src));
}
__device__ __forceinline__ void cp_commit() {
    asm volatile("cp.async.commit_group;" ::: "memory");
}
template <int N>
__device__ __forceinline__ void cp_wait() {
    asm volatile("cp.async.wait_group %0;" :: "n"(N) : "memory");
}
__device__ __forceinline__ void ldsm4(uint32_t* r, uint32_t addr) {
    asm volatile("ldmatrix.sync.aligned.m8n8.x4.shared.b16 {%0,%1,%2,%3}, [%4];"
                 : "=r"(r[0]), "=r"(r[1]), "=r"(r[2]), "=r"(r[3]) : "r"(addr));
}
__device__ __forceinline__ void mma16816(float* c, const uint32_t* a,
                                         uint32_t b0, uint32_t b1) {
    asm volatile(
        "mma.sync.aligned.m16n8k16.row.col.f32.f16.f16.f32 "
        "{%0,%1,%2,%3}, {%4,%5,%6,%7}, {%8,%9}, {%0,%1,%2,%3};"
        : "+f"(c[0]), "+f"(c[1]), "+f"(c[2]), "+f"(c[3])
        : "r"(a[0]), "r"(a[1]), "r"(a[2]), "r"(a[3]), "r"(b0), "r"(b1));
}

// ---------------- fused prep kernel ----------------
// Quantizer: levels {±(L+S), ±(L−S)}, thresholds {−L, 0, L}
// => q = sgn(w) * (L + (|w| > L ? S : -S)).
// ILP = 4 float4 loads per thread, 2x uint4 (16B) stores.
#define W_N4   (ODIM * KDIM / 4)
#define X_N4   (TOKENS * KDIM / 4)
#define WBLKS  ((W_N4 / 4 + 255) / 256)
#define XBLKS  ((X_N4 / 4 + 255) / 256)

__device__ __forceinline__ uint2 quant4(float4 v, float L, float S) {
    float m0 = L + ((fabsf(v.x) > L) ? S : -S);
    float m1 = L + ((fabsf(v.y) > L) ? S : -S);
    float m2 = L + ((fabsf(v.z) > L) ? S : -S);
    float m3 = L + ((fabsf(v.w) > L) ? S : -S);
    __half2 p0 = __floats2half2_rn(copysignf(m0, v.x), copysignf(m1, v.y));
    __half2 p1 = __floats2half2_rn(copysignf(m2, v.z), copysignf(m3, v.w));
    uint2 o;
    o.x = *reinterpret_cast<uint32_t*>(&p0);
    o.y = *reinterpret_cast<uint32_t*>(&p1);
    return o;
}
__device__ __forceinline__ uint2 cvt4(float4 v) {
    __half2 a = __floats2half2_rn(v.x, v.y);
    __half2 b = __floats2half2_rn(v.z, v.w);
    uint2 o;
    o.x = *reinterpret_cast<uint32_t*>(&a);
    o.y = *reinterpret_cast<uint32_t*>(&b);
    return o;
}

__global__ void prep_kernel(const float* __restrict__ w,
                            const float* __restrict__ x,
                            const float* __restrict__ basis) {
    int b = blockIdx.x;
    if (b < WBLKS) {
        float b0 = fabsf(basis[0]), b1 = fabsf(basis[1]);
        float L = fmaxf(b0, b1), S = fminf(b0, b1);
        int i0 = (b * blockDim.x + threadIdx.x) * 4;
        if (i0 + 3 < W_N4) {
            const float4* src = reinterpret_cast<const float4*>(w) + i0;
            float4 v0 = src[0], v1 = src[1], v2 = src[2], v3 = src[3];
            uint2 q0 = quant4(v0, L, S), q1 = quant4(v1, L, S);
            uint2 q2 = quant4(v2, L, S), q3 = quant4(v3, L, S);
            uint4* dst = reinterpret_cast<uint4*>(g_wq) + i0 / 2;
            dst[0] = make_uint4(q0.x, q0.y, q1.x, q1.y);
            dst[1] = make_uint4(q2.x, q2.y, q3.x, q3.y);
        } else {
            for (int i = i0; i < W_N4; i++) {
                float4 v = reinterpret_cast<const float4*>(w)[i];
                reinterpret_cast<uint2*>(g_wq)[i] = quant4(v, L, S);
            }
        }
    } else {
        int i0 = ((b - WBLKS) * blockDim.x + threadIdx.x) * 4;
        if (i0 + 3 < X_N4) {
            const float4* src = reinterpret_cast<const float4*>(x) + i0;
            float4 v0 = src[0], v1 = src[1], v2 = src[2], v3 = src[3];
            uint2 q0 = cvt4(v0), q1 = cvt4(v1), q2 = cvt4(v2), q3 = cvt4(v3);
            uint4* dst = reinterpret_cast<uint4*>(g_xh) + i0 / 2;
            dst[0] = make_uint4(q0.x, q0.y, q1.x, q1.y);
            dst[1] = make_uint4(q2.x, q2.y, q3.x, q3.y);
        } else {
            for (int i = i0; i < X_N4; i++) {
                float4 v = reinterpret_cast<const float4*>(x)[i];
                reinterpret_cast<uint2*>(g_xh)[i] = cvt4(v);
            }
        }
    }
}

// ---------------- GEMM ----------------
struct Ctx {
    uint32_t sb;
    uint32_t a_base0, b_base0;
    const __half* gA;
    const __half* gB;
    int tid;
};

// full stage load (A+B, one commit group) — same stream shape as R13
template <int S>
__device__ __forceinline__ void load_stage(const Ctx& c, int kt) {
    uint32_t a_off = c.sb + S * STAGE_BYTES;
    uint32_t b_off = a_off + A_STAGE_BYTES;
#pragma unroll
    for (int p = 0; p < 4; p++) {
        int id = c.tid + p * NTHREADS;
        int row = id >> 3, ch = id & 7;
        uint32_t off = (uint32_t)row * 128 + (uint32_t)ch * 16;
        cp_async16(a_off + sw128(off),
                   c.gA + (size_t)row * KDIM + kt * BK + ch * 8);
    }
#pragma unroll
    for (int p = 0; p < 4; p++) {
        int id = c.tid + p * NTHREADS;
        int row = id >> 3, ch = id & 7;
        uint32_t off = (uint32_t)row * 128 + (uint32_t)ch * 16;
        cp_async16(b_off + sw128(off),
                   c.gB + (size_t)row * KDIM + kt * BK + ch * 8);
    }
}

#define MMA_BURST(buf)                                                  \
    _Pragma("unroll")                                                   \
    for (int i = 0; i < 4; i++)                                         \
        _Pragma("unroll")                                               \
        for (int j = 0; j < 4; j++)                                     \
            mma16816(acc[i][j], af[buf][i],                             \
                     bf[buf][j >> 1][j & 1], bf[buf][j >> 1][(j & 1) + 2]);

#define LDSM_GROUP(buf, base_a, base_b, x)  do {                        \
    uint32_t _ax = (base_a) ^ (uint32_t)(x);                            \
    uint32_t _bx = (base_b) ^ (uint32_t)(x);                            \
    _Pragma("unroll")                                                   \
    for (int i = 0; i < 4; i++) ldsm4(af[buf][i], _ax + i * 2048);      \
    _Pragma("unroll")                                                   \
    for (int g = 0; g < 2; g++) ldsm4(bf[buf][g], _bx + g * 2048);      \
} while (0)

// Rotated R13 stream, race-free. Stage CUR = kt % 3 (compile-time).
// Entry: buf1 = kk3 frags of stage kt-1; all threads have cp_wait'ed for
//        stage kt (previous iteration). Every ldsm reading stage kt is
//        issued AFTER the barrier below => safe.
template <int CUR>
__device__ __forceinline__ void iter(const Ctx& c, int kt,
                                     float acc[4][4][4],
                                     uint32_t af[2][4][4],
                                     uint32_t bf[2][2][4]) {
    constexpr int LDS = (CUR + 2) % STAGES;      // slot to fill (kt+2)

    __syncthreads();                 // stage kt visible; WAR on slot LDS closed

    uint32_t a_base = c.sb + CUR * STAGE_BYTES + c.a_base0;
    uint32_t b_base = c.sb + CUR * STAGE_BYTES + A_STAGE_BYTES + c.b_base0;

    MMA_BURST(1);                        // kk3 of PREVIOUS stage (armed)
    LDSM_GROUP(0, a_base, b_base, 0);    // kk0 frags
    LDSM_GROUP(1, a_base, b_base, 32);   // kk1 frags
    MMA_BURST(0);                        // kk0
    if (kt + 2 < KT) load_stage<LDS>(c, kt + 2);   // unified burst (R13 shape)
    cp_commit();
    LDSM_GROUP(0, a_base, b_base, 64);   // kk2 frags
    MMA_BURST(1);                        // kk1
    cp_wait<1>();                        // group(kt+1) done (this thread);
                                         // skew absorbed before next barrier
    LDSM_GROUP(1, a_base, b_base, 96);   // kk3 frags (stage kt)
    MMA_BURST(0);                        // kk2
    // exit: buf1 = kk3 (consumed first thing next iteration, post-barrier)
}

__global__ void __launch_bounds__(NTHREADS, 2)
gemm_kernel(const float* __restrict__ bias, float* __restrict__ out) {
    extern __shared__ char smem[];
    Ctx c;
    c.sb = smem_to_u32(smem);
    c.tid = threadIdx.x;
    int wid = c.tid >> 5, lane = c.tid & 31;
    int warp_m = wid >> 2;            // 0..1  (64 rows each)
    int warp_n = wid & 3;             // 0..3  (32 cols each)
    int nbase = blockIdx.x * BN;
    int mbase = blockIdx.y * BM;

    c.gA = g_xh + (size_t)mbase * KDIM;
    c.gB = g_wq + (size_t)nbase * KDIM;

    float acc[4][4][4];
#pragma unroll
    for (int i = 0; i < 4; i++)
#pragma unroll
        for (int j = 0; j < 4; j++)
#pragma unroll
            for (int r = 0; r < 4; r++) acc[i][j][r] = 0.f;

    // XOR swizzle iterator: address for chunk (ch0 + 2*kk) of a row is
    //   lane_base(row) ^ (kk << 5)     [bits disjoint, no carries]
    int a_row = warp_m * 64 + ((lane >> 3) & 1) * 8 + (lane & 7);
    int b_row = warp_n * 32 + ((lane >> 3) & 1) * 8 + (lane & 7);
    int ch0 = lane >> 4;              // 0..1
    c.a_base0 = (uint32_t)a_row * 128 + 16u * (uint32_t)(ch0 ^ (a_row & 7));
    c.b_base0 = (uint32_t)b_row * 128 + 16u * (uint32_t)(ch0 ^ (b_row & 7));

    // prologue: fill stages 0,1
    load_stage<0>(c, 0); cp_commit();
    load_stage<1>(c, 1); cp_commit();

    uint32_t af[2][4][4], bf[2][2][4];

    // peeled iteration kt=0 (no previous kk3 burst)
    cp_wait<1>();                        // stage 0 done (this thread)
    __syncthreads();                     // stage 0 visible to all
    {
        uint32_t a_base = c.sb + c.a_base0;
        uint32_t b_base = c.sb + A_STAGE_BYTES + c.b_base0;
        LDSM_GROUP(0, a_base, b_base, 0);     // kk0
        LDSM_GROUP(1, a_base, b_base, 32);    // kk1
        MMA_BURST(0);                         // kk0
        load_stage<2>(c, 2);
        cp_commit();
        LDSM_GROUP(0, a_base, b_base, 64);    // kk2
        MMA_BURST(1);                         // kk1
        cp_wait<1>();                         // group(1) done
        LDSM_GROUP(1, a_base, b_base, 96);    // kk3
        MMA_BURST(0);                         // kk2
    }

    // kt = 1..63 : 63 iterations = 21 stage-constant triples <1>,<2>,<0>
#pragma unroll 1
    for (int ktb = 1; ktb < 64; ktb += 3) {
        iter<1>(c, ktb + 0, acc, af, bf);
        iter<2>(c, ktb + 1, acc, af, bf);
        iter<0>(c, ktb + 2, acc, af, bf);
    }
    // final kk3 burst of stage 63 (frags loaded at end of iter kt=63)
    MMA_BURST(1);

    // epilogue: direct to gmem with bias
    int m0 = mbase + warp_m * 64 + (lane >> 2);
    int n0 = nbase + warp_n * 32 + (lane & 3) * 2;
    float2 bj[4];
#pragma unroll
    for (int j = 0; j < 4; j++)
        bj[j] = *reinterpret_cast<const float2*>(bias + n0 + j * 8);
#pragma unroll
    for (int i = 0; i < 4; i++) {
        float* row_lo = out + (size_t)(m0 + i * 16) * ODIM;
        float* row_hi = out + (size_t)(m0 + i * 16 + 8) * ODIM;
#pragma unroll
        for (int j = 0; j < 4; j++) {
            float2 lo = { acc[i][j][0] + bj[j].x, acc[i][j][1] + bj[j].y };
            float2 hi = { acc[i][j][2] + bj[j].x, acc[i][j][3] + bj[j].y };
            *reinterpret_cast<float2*>(row_lo + n0 + j * 8) = lo;
            *reinterpret_cast<float2*>(row_hi + n0 + j * 8) = hi;
        }
    }
}

// ---------------- launch ----------------
extern "C" void kernel_launch(void* const* d_in, const int* in_sizes, int n_in,
                              void* d_out, int out_size) {
    const float* x     = (const float*)d_in[0];
    const float* w     = (const float*)d_in[1];
    const float* bias  = (const float*)d_in[2];
    const float* basis = (const float*)d_in[3];
    float* out = (float*)d_out;

    cudaFuncSetAttribute(gemm_kernel, cudaFuncAttributeMaxDynamicSharedMemorySize,
                         SMEM_TOTAL);

    prep_kernel<<<WBLKS + XBLKS, 256>>>(w, x, basis);
    gemm_kernel<<<dim3(ODIM / BN, TOKENS / BM), NTHREADS, SMEM_TOTAL>>>(bias, out);
}